// round 12
// baseline (speedup 1.0000x reference)
#include <cuda_runtime.h>
#include <cuda_bf16.h>
#include <cstdint>

// Gather: out[g][row][j*32+k] = in[row][g*512 + j*64 + k]
//   out flat float4 idx i: g=i>>20, row=(i>>6)&16383, v=i&63
//   src (float4 units) = row*1024 + g*128 + (v>>3)*16 + (v&7)
//
// R11 showed ptxas SPLIT the intended MLP=8 batch (regs=32 proves it: 8x
// float4 payload alone needs 32). This round forces the batch with inline
// asm (fixed program order): 8 ld.global.nc.v4 issued back-to-back, then 8
// st.global.v4 — on R10's proven linear grid-stride mapping with constant
// stride. Expected regs ~44-48 -> still 32-warp-cap occupancy (not
// reg-limited) at 256 thr/block.

#define GRID_BLOCKS 4096u
#define STRIDE      (GRID_BLOCKS * 256u)   // 2^20 float4s per sweep

__global__ void __launch_bounds__(256)
fuse_slice_cat_kernel(const float4* __restrict__ in, float4* __restrict__ out)
{
    const unsigned int i0 = blockIdx.x * 256u + threadIdx.x;

    const float4* pa[8];
    #pragma unroll
    for (int it = 0; it < 8; ++it) {
        unsigned int i   = i0 + (unsigned)it * STRIDE;
        unsigned int g   = i >> 20;
        unsigned int row = (i >> 6) & 16383u;
        unsigned int v   = i & 63u;
        pa[it] = in + (row * 1024u + g * 128u + (v >> 3) * 16u + (v & 7u));
    }

    float r[8][4];
    // 8 front-batched loads — asm program order prevents ptxas splitting.
    #pragma unroll
    for (int it = 0; it < 8; ++it) {
        asm volatile("ld.global.nc.v4.f32 {%0,%1,%2,%3}, [%4];"
                     : "=f"(r[it][0]), "=f"(r[it][1]),
                       "=f"(r[it][2]), "=f"(r[it][3])
                     : "l"(pa[it]));
    }

    #pragma unroll
    for (int it = 0; it < 8; ++it) {
        float4* q = out + (i0 + (unsigned)it * STRIDE);
        asm volatile("st.global.v4.f32 [%0], {%1,%2,%3,%4};"
                     :: "l"(q),
                        "f"(r[it][0]), "f"(r[it][1]),
                        "f"(r[it][2]), "f"(r[it][3])
                     : "memory");
    }
}

extern "C" void kernel_launch(void* const* d_in, const int* in_sizes, int n_in,
                              void* d_out, int out_size)
{
    const float4* in  = (const float4*)d_in[0];
    float4*       out = (float4*)d_out;

    // 2^23 float4s total; 8 per thread -> 4096 blocks of 256.
    fuse_slice_cat_kernel<<<GRID_BLOCKS, 256>>>(in, out);
}

// round 13
// speedup vs baseline: 1.0185x; 1.0185x over previous
#include <cuda_runtime.h>
#include <cuda_bf16.h>
#include <cstdint>

// Gather: out[g][row][j*32+k] = in[row][g*512 + j*64 + k]
//   out flat float4 idx i: g=i>>20, row=(i>>6)&16383, v=i&63
//   src (float4 units) = row*1024 + g*128 + (v>>3)*16 + (v&7)
//
// TERMINAL KERNEL (R10, best of 12 rounds: 44.128us).
//   * front-batched MLP=4 per thread at regs=30 -> occ 84.5% (the sweet
//     spot: MLP=8 was tried 3 ways and always re-serialized or regressed),
//   * compile-time-constant grid stride (2^21),
//   * linear grid-stride mapping (beat block-contiguous and group-fastest
//     remaps).
// Steady state is the structural roofline: 256 MiB/replay irreducible
// traffic (half-dense reads + dense writes, no reuse) at ~5.9 TB/s.
// Falsified levers: deeper MLP, 256-bit accesses, every L2 eviction-class
// residency scheme, concurrency remaps, block-granularity tuning.

#define GRID_BLOCKS 8192u
#define STRIDE      (GRID_BLOCKS * 256u)   // 2^21 float4s

__global__ void __launch_bounds__(256)
fuse_slice_cat_kernel(const float4* __restrict__ in, float4* __restrict__ out)
{
    const unsigned int i0 = blockIdx.x * 256u + threadIdx.x;

    unsigned int idx[4];
    unsigned int srcI[4];

    #pragma unroll
    for (int it = 0; it < 4; ++it) {
        unsigned int i   = i0 + (unsigned)it * STRIDE;
        unsigned int g   = i >> 20;
        unsigned int row = (i >> 6) & 16383u;
        unsigned int v   = i & 63u;
        idx[it]  = i;
        srcI[it] = row * 1024u + g * 128u + (v >> 3) * 16u + (v & 7u);
    }

    float4 r[4];
    #pragma unroll
    for (int it = 0; it < 4; ++it)      // 4 loads in flight before any store
        r[it] = in[srcI[it]];

    #pragma unroll
    for (int it = 0; it < 4; ++it)
        out[idx[it]] = r[it];
}

extern "C" void kernel_launch(void* const* d_in, const int* in_sizes, int n_in,
                              void* d_out, int out_size)
{
    const float4* in  = (const float4*)d_in[0];
    float4*       out = (float4*)d_out;

    fuse_slice_cat_kernel<<<GRID_BLOCKS, 256>>>(in, out);
}